// round 9
// baseline (speedup 1.0000x reference)
#include <cuda_runtime.h>
#include <cuda_bf16.h>
#include <cuda_fp16.h>
#include <cstdint>
#include <math.h>

#define DIM      128
#define HEADS    8
#define NMAX     100000
#define EMAX     1600000
#define SCAN_BLK 1024
#define MAX_BLKS ((NMAX + SCAN_BLK - 1) / SCAN_BLK + 2)

// ---------------- device scratch (allocation-free rule) ----------------
__device__ __half g_nth[(size_t)NMAX * DIM]; // transformed node features (fp16)
__device__ float g_es[(size_t)NMAX * HEADS]; // exp(sender score)
__device__ int   g_cnt[NMAX];                // in-degree counts (kept zeroed)
__device__ int   g_row[NMAX + 1];            // CSR row offsets
__device__ int   g_fill[NMAX];               // fill cursors
__device__ int   g_csr[EMAX];                // CSR payload: sender ids
__device__ int   g_bsum[MAX_BLKS];           // scan block sums

__device__ __forceinline__ float lrelu(float x) { return x > 0.0f ? x : 0.2f * x; }

__device__ __forceinline__ uint32_t smem_u32(const void* p) {
    uint32_t a;
    asm("{ .reg .u64 t; cvta.to.shared.u64 t, %1; cvt.u32.u64 %0, t; }" : "=r"(a) : "l"(p));
    return a;
}

// swizzled byte offset inside a [rows][128 bf16] tile (256B rows)
__device__ __forceinline__ uint32_t toff(int row, int k) {
    return (uint32_t)(row * 256 + ((((k >> 3) ^ (row & 7)) & 15) << 4) + ((k & 7) << 1));
}

#define LDSM4(r, addr) asm volatile( \
    "ldmatrix.sync.aligned.m8n8.x4.shared.b16 {%0,%1,%2,%3}, [%4];" \
    : "=r"((r)[0]), "=r"((r)[1]), "=r"((r)[2]), "=r"((r)[3]) : "r"(addr))
#define LDSM2(r, addr) asm volatile( \
    "ldmatrix.sync.aligned.m8n8.x2.shared.b16 {%0,%1}, [%2];" \
    : "=r"((r)[0]), "=r"((r)[1]) : "r"(addr))
#define MMA(c, a, b) asm volatile( \
    "mma.sync.aligned.m16n8k16.row.col.f32.bf16.bf16.f32 " \
    "{%0,%1,%2,%3},{%4,%5,%6,%7},{%8,%9},{%0,%1,%2,%3};" \
    : "+f"((c)[0]), "+f"((c)[1]), "+f"((c)[2]), "+f"((c)[3]) \
    : "r"((a)[0]), "r"((a)[1]), "r"((a)[2]), "r"((a)[3]), "r"((b)[0]), "r"((b)[1]))

// ---------------------------------------------------------------------------
// GEMM: bf16-split mma.sync, 128-row tiles. W converted fp32->bf16 hi/lo
// in-block (no prep kernel). Epilogue: +bias, store nt (fp16),
// fused per-head score -> g_es = exp(score).
// ---------------------------------------------------------------------------
#define SM_AHI 0
#define SM_ALO 32768
#define SM_BHI 65536
#define SM_BLO 98304
#define SM_TOTAL 131072

__global__ __launch_bounds__(256, 1)
void gemm_mma_kernel(const float* __restrict__ A, const float* __restrict__ W,
                     const float* __restrict__ bias, const float* __restrict__ attn_w,
                     int N) {
    extern __shared__ __align__(1024) char smem[];
    const uint32_t sb = smem_u32(smem);
    const int tid = threadIdx.x;
    const int wid = tid >> 5;
    const int lane = tid & 31;
    const int row0 = blockIdx.x * 128;

    // convert W (fp32 [k][n]) into bf16 hi/lo Bt[n][k] swizzled smem tiles
    for (int i = 0; i < 16; i++) {
        int idx4 = tid + i * 256;          // 0..4095 float4s of W
        int k = idx4 >> 5;
        int n4 = (idx4 & 31) * 4;
        float4 v = *reinterpret_cast<const float4*>(&W[(size_t)k * DIM + n4]);
        float xs[4] = {v.x, v.y, v.z, v.w};
#pragma unroll
        for (int j = 0; j < 4; j++) {
            __nv_bfloat16 h = __float2bfloat16(xs[j]);
            __nv_bfloat16 l = __float2bfloat16(xs[j] - __bfloat162float(h));
            uint32_t so = toff(n4 + j, k);   // B is transposed: row=n, col=k
            *reinterpret_cast<__nv_bfloat16*>(smem + SM_BHI + so) = h;
            *reinterpret_cast<__nv_bfloat16*>(smem + SM_BLO + so) = l;
        }
    }
    // load A tile (128 x 128 fp32), split hi/lo bf16, store swizzled
    for (int i = 0; i < 16; i++) {
        int idx4 = tid + i * 256;
        int r = idx4 >> 5;
        int c4 = (idx4 & 31) * 4;
        float4 v = make_float4(0.f, 0.f, 0.f, 0.f);
        if (row0 + r < N)
            v = *reinterpret_cast<const float4*>(&A[(size_t)(row0 + r) * DIM + c4]);
        float xs[4] = {v.x, v.y, v.z, v.w};
        __nv_bfloat16 hs[4], ls[4];
#pragma unroll
        for (int j = 0; j < 4; j++) {
            hs[j] = __float2bfloat16(xs[j]);
            ls[j] = __float2bfloat16(xs[j] - __bfloat162float(hs[j]));
        }
        uint32_t so = toff(r, c4);
        *reinterpret_cast<__nv_bfloat162*>(smem + SM_AHI + so)     = __halves2bfloat162(hs[0], hs[1]);
        *reinterpret_cast<__nv_bfloat162*>(smem + SM_AHI + so + 4) = __halves2bfloat162(hs[2], hs[3]);
        *reinterpret_cast<__nv_bfloat162*>(smem + SM_ALO + so)     = __halves2bfloat162(ls[0], ls[1]);
        *reinterpret_cast<__nv_bfloat162*>(smem + SM_ALO + so + 4) = __halves2bfloat162(ls[2], ls[3]);
    }
    __syncthreads();

    const int wm = wid >> 2;
    const int wn = wid & 3;
    const int r_base = wm * 64;
    const int n_base = wn * 32;

    float acc[4][4][4];
#pragma unroll
    for (int mi = 0; mi < 4; mi++)
#pragma unroll
        for (int ni = 0; ni < 4; ni++)
#pragma unroll
            for (int q = 0; q < 4; q++) acc[mi][ni][q] = 0.0f;

    const int L = lane & 15;
#pragma unroll
    for (int ks = 0; ks < 8; ks++) {
        uint32_t ah[4][4], al[4][4], bh[4][2], bl[4][2];
        const int ka = ks * 16 + (lane >> 4) * 8;
        const int kb = ks * 16 + ((L >> 3) & 1) * 8;
#pragma unroll
        for (int mi = 0; mi < 4; mi++) {
            uint32_t off = toff(r_base + mi * 16 + L, ka);
            LDSM4(ah[mi], sb + SM_AHI + off);
            LDSM4(al[mi], sb + SM_ALO + off);
        }
#pragma unroll
        for (int ni = 0; ni < 4; ni++) {
            uint32_t off = toff(n_base + ni * 8 + (L & 7), kb);
            LDSM2(bh[ni], sb + SM_BHI + off);
            LDSM2(bl[ni], sb + SM_BLO + off);
        }
#pragma unroll
        for (int mi = 0; mi < 4; mi++)
#pragma unroll
            for (int ni = 0; ni < 4; ni++) {
                MMA(acc[mi][ni], ah[mi], bh[ni]);
                MMA(acc[mi][ni], ah[mi], bl[ni]);
                MMA(acc[mi][ni], al[mi], bh[ni]);
            }
    }

    // ---- epilogue ----
    float aw[16];
#pragma unroll
    for (int j = 0; j < 16; j++) aw[j] = __ldg(&attn_w[j]);

    float sp[8][2];
#pragma unroll
    for (int q = 0; q < 8; q++) { sp[q][0] = 0.0f; sp[q][1] = 0.0f; }

#pragma unroll
    for (int ni = 0; ni < 4; ni++) {
        int n0 = n_base + ni * 8 + (lane & 3) * 2;
        float bw0 = __ldg(&bias[n0]), bw1 = __ldg(&bias[n0 + 1]);
        float aw0 = aw[n0 & 15], aw1 = aw[(n0 + 1) & 15];
        int hl = ni >> 1;
#pragma unroll
        for (int mi = 0; mi < 4; mi++) {
            float c0 = acc[mi][ni][0] + bw0, c1 = acc[mi][ni][1] + bw1;
            float c2 = acc[mi][ni][2] + bw0, c3 = acc[mi][ni][3] + bw1;
            int ra = row0 + r_base + mi * 16 + (lane >> 2);
            int rb = ra + 8;
            if (ra < N) *reinterpret_cast<__half2*>(&g_nth[(size_t)ra * DIM + n0]) = __floats2half2_rn(c0, c1);
            if (rb < N) *reinterpret_cast<__half2*>(&g_nth[(size_t)rb * DIM + n0]) = __floats2half2_rn(c2, c3);
            sp[mi * 2 + 0][hl] += lrelu(c0) * aw0 + lrelu(c1) * aw1;
            sp[mi * 2 + 1][hl] += lrelu(c2) * aw0 + lrelu(c3) * aw1;
        }
    }
#pragma unroll
    for (int slot = 0; slot < 8; slot++)
#pragma unroll
        for (int hl = 0; hl < 2; hl++) {
            float v = sp[slot][hl];
            v += __shfl_xor_sync(0xffffffffu, v, 1);
            v += __shfl_xor_sync(0xffffffffu, v, 2);
            if ((lane & 3) == 0) {
                int row = row0 + r_base + (slot >> 1) * 16 + (slot & 1) * 8 + (lane >> 2);
                if (row < N) g_es[(size_t)row * HEADS + wn * 2 + hl] = __expf(v);
            }
        }
}

// ---------------------------------------------------------------------------
// CSR build: count -> scan1 -> scan23 -> fill   (side stream)
// ---------------------------------------------------------------------------
__global__ void count_kernel(const int* __restrict__ receivers, int E) {
    int t = blockIdx.x * blockDim.x + threadIdx.x;
    int e0 = t * 4;
    if (e0 + 3 < E) {
        int4 r = *reinterpret_cast<const int4*>(&receivers[e0]);
        atomicAdd(&g_cnt[r.x], 1);
        atomicAdd(&g_cnt[r.y], 1);
        atomicAdd(&g_cnt[r.z], 1);
        atomicAdd(&g_cnt[r.w], 1);
    } else {
        for (int e = e0; e < E; e++) atomicAdd(&g_cnt[receivers[e]], 1);
    }
}

__global__ __launch_bounds__(SCAN_BLK)
void scan1_kernel(int N) {
    __shared__ int wsum[32];
    int i = blockIdx.x * SCAN_BLK + threadIdx.x;
    int lane = threadIdx.x & 31, w = threadIdx.x >> 5;
    int v = 0;
    if (i < N) { v = g_cnt[i]; g_cnt[i] = 0; }   // read + re-zero for replay
    int incl = v;
#pragma unroll
    for (int o = 1; o < 32; o <<= 1) {
        int t = __shfl_up_sync(0xffffffffu, incl, o);
        if (lane >= o) incl += t;
    }
    if (lane == 31) wsum[w] = incl;
    __syncthreads();
    if (w == 0) {
        int s = wsum[lane];
#pragma unroll
        for (int o = 1; o < 32; o <<= 1) {
            int t = __shfl_up_sync(0xffffffffu, s, o);
            if (lane >= o) s += t;
        }
        wsum[lane] = s;
    }
    __syncthreads();
    int woff = (w > 0) ? wsum[w - 1] : 0;
    if (i < N) g_row[i] = woff + incl - v;       // exclusive (block-local)
    if (threadIdx.x == SCAN_BLK - 1) g_bsum[blockIdx.x] = woff + incl;
}

// scan2 merged into scan3: each block (256 idxs, all in one SCAN_BLK group)
// reduces the g_bsum prefix it needs with warp 0, then applies it.
__global__ void scan23_kernel(int N, int E) {
    __shared__ int soff;
    int i = blockIdx.x * blockDim.x + threadIdx.x;
    int g = (int)((blockIdx.x * blockDim.x) / SCAN_BLK);   // bsum prefix length
    if (threadIdx.x < 32) {
        int lane = threadIdx.x;
        int acc = 0;
        for (int b = lane; b < g; b += 32) acc += g_bsum[b];
#pragma unroll
        for (int o = 16; o > 0; o >>= 1) acc += __shfl_xor_sync(0xffffffffu, acc, o);
        if (lane == 0) soff = acc;
    }
    __syncthreads();
    if (i < N) {
        int r = g_row[i] + soff;
        g_row[i] = r;
        g_fill[i] = r;
    }
    if (i == 0) g_row[N] = E;
}

__global__ void fill_kernel(const int* __restrict__ senders,
                            const int* __restrict__ receivers, int E) {
    int t = blockIdx.x * blockDim.x + threadIdx.x;
    int e0 = t * 4;
    if (e0 + 3 < E) {
        int4 r = *reinterpret_cast<const int4*>(&receivers[e0]);
        int4 s = *reinterpret_cast<const int4*>(&senders[e0]);
        g_csr[atomicAdd(&g_fill[r.x], 1)] = s.x;
        g_csr[atomicAdd(&g_fill[r.y], 1)] = s.y;
        g_csr[atomicAdd(&g_fill[r.z], 1)] = s.z;
        g_csr[atomicAdd(&g_fill[r.w], 1)] = s.w;
    } else {
        for (int e = e0; e < E; e++)
            g_csr[atomicAdd(&g_fill[receivers[e]], 1)] = senders[e];
    }
}

// ---------------------------------------------------------------------------
// Fused node kernel v3: 16 lanes/node (2 nodes/warp), masked 4-edge blocks
// (tail edges clamped + zero-weighted so all loads stay in flight).
// ---------------------------------------------------------------------------
__device__ __forceinline__ void accum8(float2* a, uint4 u, float w) {
    float2 p0 = __half22float2(*reinterpret_cast<__half2*>(&u.x));
    float2 p1 = __half22float2(*reinterpret_cast<__half2*>(&u.y));
    float2 p2 = __half22float2(*reinterpret_cast<__half2*>(&u.z));
    float2 p3 = __half22float2(*reinterpret_cast<__half2*>(&u.w));
    a[0].x += w * p0.x; a[0].y += w * p0.y;
    a[1].x += w * p1.x; a[1].y += w * p1.y;
    a[2].x += w * p2.x; a[2].y += w * p2.y;
    a[3].x += w * p3.x; a[3].y += w * p3.y;
}

__global__ __launch_bounds__(256)
void node_accum_kernel(float* __restrict__ out, int N) {
    int warp = (blockIdx.x * blockDim.x + threadIdx.x) >> 5;
    int lane = threadIdx.x & 31;
    int node = warp * 2 + (lane >> 4);
    int sl = lane & 15;
    if (node >= N) return;

    int start = g_row[node];
    int end   = g_row[node + 1];
    float* outp = out + (size_t)node * DIM + sl * 8;

    if (start == end) {
        *reinterpret_cast<float4*>(outp)     = make_float4(0.f, 0.f, 0.f, 0.f);
        *reinterpret_cast<float4*>(outp + 4) = make_float4(0.f, 0.f, 0.f, 0.f);
        return;
    }

    const int h2 = sl >> 1;
    const __half* ntb = g_nth;
    float2 acc[4];
    acc[0] = acc[1] = acc[2] = acc[3] = make_float2(0.f, 0.f);
    float denom = 0.0f;

    for (int j = start; j < end; j += 4) {
        int j1 = j + 1, j2 = j + 2, j3 = j + 3;
        bool b1 = j1 < end, b2 = j2 < end, b3 = j3 < end;
        int s0 = __ldg(&g_csr[j]);
        int s1 = __ldg(&g_csr[b1 ? j1 : j]);
        int s2 = __ldg(&g_csr[b2 ? j2 : j]);
        int s3 = __ldg(&g_csr[b3 ? j3 : j]);
        float w0 = g_es[(size_t)s0 * HEADS + h2];
        float w1 = g_es[(size_t)s1 * HEADS + h2];
        float w2 = g_es[(size_t)s2 * HEADS + h2];
        float w3 = g_es[(size_t)s3 * HEADS + h2];
        uint4 u0 = *reinterpret_cast<const uint4*>(&ntb[(size_t)s0 * DIM + sl * 8]);
        uint4 u1 = *reinterpret_cast<const uint4*>(&ntb[(size_t)s1 * DIM + sl * 8]);
        uint4 u2 = *reinterpret_cast<const uint4*>(&ntb[(size_t)s2 * DIM + sl * 8]);
        uint4 u3 = *reinterpret_cast<const uint4*>(&ntb[(size_t)s3 * DIM + sl * 8]);
        if (!b1) w1 = 0.0f;
        if (!b2) w2 = 0.0f;
        if (!b3) w3 = 0.0f;
        accum8(acc, u0, w0);
        accum8(acc, u1, w1);
        accum8(acc, u2, w2);
        accum8(acc, u3, w3);
        denom += (w0 + w1) + (w2 + w3);
    }

    float inv = 1.0f / denom;
    *reinterpret_cast<float4*>(outp) =
        make_float4(acc[0].x * inv, acc[0].y * inv, acc[1].x * inv, acc[1].y * inv);
    *reinterpret_cast<float4*>(outp + 4) =
        make_float4(acc[2].x * inv, acc[2].y * inv, acc[3].x * inv, acc[3].y * inv);
}

// ---------------------------------------------------------------------------
extern "C" void kernel_launch(void* const* d_in, const int* in_sizes, int n_in,
                              void* d_out, int out_size) {
    const float* nodes     = (const float*)d_in[0];
    const int*   senders   = (const int*)d_in[1];
    const int*   receivers = (const int*)d_in[2];
    const float* W         = (const float*)d_in[3];
    const float* b         = (const float*)d_in[4];
    const float* attn_w    = (const float*)d_in[5];
    // attn_b (d_in[6]) cancels in the segment softmax

    const int N = in_sizes[0] / DIM;
    const int E = in_sizes[1];
    float* out = (float*)d_out;

    const int nb = (N + SCAN_BLK - 1) / SCAN_BLK;
    const int tiles = (N + 127) / 128;
    const int e4blocks = ((E + 3) / 4 + 255) / 256;

    static cudaStream_t s_side = nullptr;
    static cudaEvent_t ev_fork = nullptr, ev_join = nullptr;
    if (!s_side) {
        cudaStreamCreateWithFlags(&s_side, cudaStreamNonBlocking);
        cudaEventCreateWithFlags(&ev_fork, cudaEventDisableTiming);
        cudaEventCreateWithFlags(&ev_join, cudaEventDisableTiming);
        cudaFuncSetAttribute(gemm_mma_kernel,
                             cudaFuncAttributeMaxDynamicSharedMemorySize, SM_TOTAL);
    }

    // fork: CSR build on side stream, GEMM on main stream
    cudaEventRecord(ev_fork, 0);
    cudaStreamWaitEvent(s_side, ev_fork, 0);

    count_kernel<<<e4blocks, 256, 0, s_side>>>(receivers, E);
    scan1_kernel<<<nb, SCAN_BLK, 0, s_side>>>(N);
    scan23_kernel<<<(N + 255) / 256, 256, 0, s_side>>>(N, E);
    fill_kernel<<<e4blocks, 256, 0, s_side>>>(senders, receivers, E);

    gemm_mma_kernel<<<tiles, 256, SM_TOTAL>>>(nodes, W, b, attn_w, N);

    // join
    cudaEventRecord(ev_join, s_side);
    cudaStreamWaitEvent(0, ev_join, 0);

    node_accum_kernel<<<(N * 16 + 255) / 256, 256>>>(out, N);
}

// round 10
// speedup vs baseline: 1.2141x; 1.2141x over previous
#include <cuda_runtime.h>
#include <cuda_bf16.h>
#include <cuda_fp16.h>
#include <cstdint>
#include <math.h>

#define DIM      128
#define HEADS    8
#define NMAX     100000
#define EMAX     1600000
#define SCAN_BLK 1024
#define MAX_BLKS ((NMAX + SCAN_BLK - 1) / SCAN_BLK + 2)

// ---------------- device scratch (allocation-free rule) ----------------
__device__ __half g_nth[(size_t)NMAX * DIM]; // transformed node features (fp16)
__device__ float g_es[(size_t)NMAX * HEADS]; // exp(sender score)
__device__ int   g_cnt[NMAX];                // in-degree counts (kept zeroed)
__device__ int   g_row[NMAX + 1];            // CSR row offsets
__device__ int   g_fill[NMAX];               // fill cursors
__device__ int   g_csr[EMAX];                // CSR payload: sender ids
__device__ int   g_bsum[MAX_BLKS];           // scan block sums
// W as bf16 hi/lo images, layout Bt[n][k] row-major with ldmatrix swizzle
__device__ __align__(16) char g_Bhi[32768];
__device__ __align__(16) char g_Blo[32768];

__device__ __forceinline__ float lrelu(float x) { return x > 0.0f ? x : 0.2f * x; }

__device__ __forceinline__ uint32_t smem_u32(const void* p) {
    uint32_t a;
    asm("{ .reg .u64 t; cvta.to.shared.u64 t, %1; cvt.u32.u64 %0, t; }" : "=r"(a) : "l"(p));
    return a;
}

// swizzled byte offset inside a [rows][128 bf16] tile (256B rows)
__device__ __forceinline__ uint32_t toff(int row, int k) {
    return (uint32_t)(row * 256 + ((((k >> 3) ^ (row & 7)) & 15) << 4) + ((k & 7) << 1));
}

#define LDSM4(r, addr) asm volatile( \
    "ldmatrix.sync.aligned.m8n8.x4.shared.b16 {%0,%1,%2,%3}, [%4];" \
    : "=r"((r)[0]), "=r"((r)[1]), "=r"((r)[2]), "=r"((r)[3]) : "r"(addr))
#define LDSM2(r, addr) asm volatile( \
    "ldmatrix.sync.aligned.m8n8.x2.shared.b16 {%0,%1}, [%2];" \
    : "=r"((r)[0]), "=r"((r)[1]) : "r"(addr))
#define MMA(c, a, b) asm volatile( \
    "mma.sync.aligned.m16n8k16.row.col.f32.bf16.bf16.f32 " \
    "{%0,%1,%2,%3},{%4,%5,%6,%7},{%8,%9},{%0,%1,%2,%3};" \
    : "+f"((c)[0]), "+f"((c)[1]), "+f"((c)[2]), "+f"((c)[3]) \
    : "r"((a)[0]), "r"((a)[1]), "r"((a)[2]), "r"((a)[3]), "r"((b)[0]), "r"((b)[1]))

// ---------------------------------------------------------------------------
// prep: W (fp32 [k][n]) -> bf16 hi/lo Bt[n][k] swizzled images (once, global)
// ---------------------------------------------------------------------------
__global__ void prep_w_kernel(const float* __restrict__ W) {
    int t = blockIdx.x * blockDim.x + threadIdx.x;
    if (t >= DIM * DIM) return;
    int k = t >> 7, n = t & 127;
    float x = W[k * DIM + n];
    __nv_bfloat16 h = __float2bfloat16(x);
    __nv_bfloat16 l = __float2bfloat16(x - __bfloat162float(h));
    uint32_t so = toff(n, k);
    *reinterpret_cast<__nv_bfloat16*>(g_Bhi + so) = h;
    *reinterpret_cast<__nv_bfloat16*>(g_Blo + so) = l;
}

// ---------------------------------------------------------------------------
// GEMM: bf16-split mma.sync, 128-row tiles. Epilogue: +bias, store nt (fp16),
// fused per-head score -> g_es = exp(score).
// ---------------------------------------------------------------------------
#define SM_AHI 0
#define SM_ALO 32768
#define SM_BHI 65536
#define SM_BLO 98304
#define SM_TOTAL 131072

__global__ __launch_bounds__(256, 1)
void gemm_mma_kernel(const float* __restrict__ A, const float* __restrict__ bias,
                     const float* __restrict__ attn_w, int N) {
    extern __shared__ __align__(1024) char smem[];
    const uint32_t sb = smem_u32(smem);
    const int tid = threadIdx.x;
    const int wid = tid >> 5;
    const int lane = tid & 31;
    const int row0 = blockIdx.x * 128;

    {
        const int4* shi = reinterpret_cast<const int4*>(g_Bhi);
        const int4* slo = reinterpret_cast<const int4*>(g_Blo);
        int4* dhi = reinterpret_cast<int4*>(smem + SM_BHI);
        int4* dlo = reinterpret_cast<int4*>(smem + SM_BLO);
        for (int i = tid; i < 2048; i += 256) { dhi[i] = shi[i]; dlo[i] = slo[i]; }
    }
    for (int i = 0; i < 16; i++) {
        int idx4 = tid + i * 256;
        int r = idx4 >> 5;
        int c4 = (idx4 & 31) * 4;
        float4 v = make_float4(0.f, 0.f, 0.f, 0.f);
        if (row0 + r < N)
            v = *reinterpret_cast<const float4*>(&A[(size_t)(row0 + r) * DIM + c4]);
        float xs[4] = {v.x, v.y, v.z, v.w};
        __nv_bfloat16 hs[4], ls[4];
#pragma unroll
        for (int j = 0; j < 4; j++) {
            hs[j] = __float2bfloat16(xs[j]);
            ls[j] = __float2bfloat16(xs[j] - __bfloat162float(hs[j]));
        }
        uint32_t so = toff(r, c4);
        *reinterpret_cast<__nv_bfloat162*>(smem + SM_AHI + so)     = __halves2bfloat162(hs[0], hs[1]);
        *reinterpret_cast<__nv_bfloat162*>(smem + SM_AHI + so + 4) = __halves2bfloat162(hs[2], hs[3]);
        *reinterpret_cast<__nv_bfloat162*>(smem + SM_ALO + so)     = __halves2bfloat162(ls[0], ls[1]);
        *reinterpret_cast<__nv_bfloat162*>(smem + SM_ALO + so + 4) = __halves2bfloat162(ls[2], ls[3]);
    }
    __syncthreads();

    const int wm = wid >> 2;
    const int wn = wid & 3;
    const int r_base = wm * 64;
    const int n_base = wn * 32;

    float acc[4][4][4];
#pragma unroll
    for (int mi = 0; mi < 4; mi++)
#pragma unroll
        for (int ni = 0; ni < 4; ni++)
#pragma unroll
            for (int q = 0; q < 4; q++) acc[mi][ni][q] = 0.0f;

    const int L = lane & 15;
#pragma unroll
    for (int ks = 0; ks < 8; ks++) {
        uint32_t ah[4][4], al[4][4], bh[4][2], bl[4][2];
        const int ka = ks * 16 + (lane >> 4) * 8;
        const int kb = ks * 16 + ((L >> 3) & 1) * 8;
#pragma unroll
        for (int mi = 0; mi < 4; mi++) {
            uint32_t off = toff(r_base + mi * 16 + L, ka);
            LDSM4(ah[mi], sb + SM_AHI + off);
            LDSM4(al[mi], sb + SM_ALO + off);
        }
#pragma unroll
        for (int ni = 0; ni < 4; ni++) {
            uint32_t off = toff(n_base + ni * 8 + (L & 7), kb);
            LDSM2(bh[ni], sb + SM_BHI + off);
            LDSM2(bl[ni], sb + SM_BLO + off);
        }
#pragma unroll
        for (int mi = 0; mi < 4; mi++)
#pragma unroll
            for (int ni = 0; ni < 4; ni++) {
                MMA(acc[mi][ni], ah[mi], bh[ni]);
                MMA(acc[mi][ni], ah[mi], bl[ni]);
                MMA(acc[mi][ni], al[mi], bh[ni]);
            }
    }

    // ---- epilogue ----
    float aw[16];
#pragma unroll
    for (int j = 0; j < 16; j++) aw[j] = __ldg(&attn_w[j]);

    float sp[8][2];
#pragma unroll
    for (int q = 0; q < 8; q++) { sp[q][0] = 0.0f; sp[q][1] = 0.0f; }

#pragma unroll
    for (int ni = 0; ni < 4; ni++) {
        int n0 = n_base + ni * 8 + (lane & 3) * 2;
        float bw0 = __ldg(&bias[n0]), bw1 = __ldg(&bias[n0 + 1]);
        float aw0 = aw[n0 & 15], aw1 = aw[(n0 + 1) & 15];
        int hl = ni >> 1;
#pragma unroll
        for (int mi = 0; mi < 4; mi++) {
            float c0 = acc[mi][ni][0] + bw0, c1 = acc[mi][ni][1] + bw1;
            float c2 = acc[mi][ni][2] + bw0, c3 = acc[mi][ni][3] + bw1;
            int ra = row0 + r_base + mi * 16 + (lane >> 2);
            int rb = ra + 8;
            if (ra < N) *reinterpret_cast<__half2*>(&g_nth[(size_t)ra * DIM + n0]) = __floats2half2_rn(c0, c1);
            if (rb < N) *reinterpret_cast<__half2*>(&g_nth[(size_t)rb * DIM + n0]) = __floats2half2_rn(c2, c3);
            sp[mi * 2 + 0][hl] += lrelu(c0) * aw0 + lrelu(c1) * aw1;
            sp[mi * 2 + 1][hl] += lrelu(c2) * aw0 + lrelu(c3) * aw1;
        }
    }
#pragma unroll
    for (int slot = 0; slot < 8; slot++)
#pragma unroll
        for (int hl = 0; hl < 2; hl++) {
            float v = sp[slot][hl];
            v += __shfl_xor_sync(0xffffffffu, v, 1);
            v += __shfl_xor_sync(0xffffffffu, v, 2);
            if ((lane & 3) == 0) {
                int row = row0 + r_base + (slot >> 1) * 16 + (slot & 1) * 8 + (lane >> 2);
                if (row < N) g_es[(size_t)row * HEADS + wn * 2 + hl] = __expf(v);
            }
        }
}

// ---------------------------------------------------------------------------
// CSR build: count -> scan1 -> scan23 -> fill  (side stream)
// count/fill: 8 edges per thread to double atomic MLP (latency-bound).
// ---------------------------------------------------------------------------
__global__ void count_kernel(const int* __restrict__ receivers, int E) {
    int t = blockIdx.x * blockDim.x + threadIdx.x;
    int e0 = t * 8;
    if (e0 + 7 < E) {
        int4 ra = *reinterpret_cast<const int4*>(&receivers[e0]);
        int4 rb = *reinterpret_cast<const int4*>(&receivers[e0 + 4]);
        atomicAdd(&g_cnt[ra.x], 1); atomicAdd(&g_cnt[ra.y], 1);
        atomicAdd(&g_cnt[ra.z], 1); atomicAdd(&g_cnt[ra.w], 1);
        atomicAdd(&g_cnt[rb.x], 1); atomicAdd(&g_cnt[rb.y], 1);
        atomicAdd(&g_cnt[rb.z], 1); atomicAdd(&g_cnt[rb.w], 1);
    } else {
        for (int e = e0; e < E; e++) atomicAdd(&g_cnt[receivers[e]], 1);
    }
}

__global__ __launch_bounds__(SCAN_BLK)
void scan1_kernel(int N) {
    __shared__ int wsum[32];
    int i = blockIdx.x * SCAN_BLK + threadIdx.x;
    int lane = threadIdx.x & 31, w = threadIdx.x >> 5;
    int v = 0;
    if (i < N) { v = g_cnt[i]; g_cnt[i] = 0; }   // read + re-zero for replay
    int incl = v;
#pragma unroll
    for (int o = 1; o < 32; o <<= 1) {
        int t = __shfl_up_sync(0xffffffffu, incl, o);
        if (lane >= o) incl += t;
    }
    if (lane == 31) wsum[w] = incl;
    __syncthreads();
    if (w == 0) {
        int s = wsum[lane];
#pragma unroll
        for (int o = 1; o < 32; o <<= 1) {
            int t = __shfl_up_sync(0xffffffffu, s, o);
            if (lane >= o) s += t;
        }
        wsum[lane] = s;
    }
    __syncthreads();
    int woff = (w > 0) ? wsum[w - 1] : 0;
    if (i < N) g_row[i] = woff + incl - v;       // exclusive (block-local)
    if (threadIdx.x == SCAN_BLK - 1) g_bsum[blockIdx.x] = woff + incl;
}

// scan2 merged into scan3: warp 0 of each block reduces its g_bsum prefix.
// (256-thread blocks always lie inside a single SCAN_BLK group.)
__global__ void scan23_kernel(int N, int E) {
    __shared__ int soff;
    int i = blockIdx.x * blockDim.x + threadIdx.x;
    int g = (int)((blockIdx.x * blockDim.x) / SCAN_BLK);
    if (threadIdx.x < 32) {
        int lane = threadIdx.x;
        int acc = 0;
        for (int b = lane; b < g; b += 32) acc += g_bsum[b];
#pragma unroll
        for (int o = 16; o > 0; o >>= 1) acc += __shfl_xor_sync(0xffffffffu, acc, o);
        if (lane == 0) soff = acc;
    }
    __syncthreads();
    if (i < N) {
        int r = g_row[i] + soff;
        g_row[i] = r;
        g_fill[i] = r;
    }
    if (i == 0) g_row[N] = E;
}

__global__ void fill_kernel(const int* __restrict__ senders,
                            const int* __restrict__ receivers, int E) {
    int t = blockIdx.x * blockDim.x + threadIdx.x;
    int e0 = t * 8;
    if (e0 + 7 < E) {
        int4 ra = *reinterpret_cast<const int4*>(&receivers[e0]);
        int4 rb = *reinterpret_cast<const int4*>(&receivers[e0 + 4]);
        int4 sa = *reinterpret_cast<const int4*>(&senders[e0]);
        int4 sb = *reinterpret_cast<const int4*>(&senders[e0 + 4]);
        int p0 = atomicAdd(&g_fill[ra.x], 1);
        int p1 = atomicAdd(&g_fill[ra.y], 1);
        int p2 = atomicAdd(&g_fill[ra.z], 1);
        int p3 = atomicAdd(&g_fill[ra.w], 1);
        int p4 = atomicAdd(&g_fill[rb.x], 1);
        int p5 = atomicAdd(&g_fill[rb.y], 1);
        int p6 = atomicAdd(&g_fill[rb.z], 1);
        int p7 = atomicAdd(&g_fill[rb.w], 1);
        g_csr[p0] = sa.x; g_csr[p1] = sa.y; g_csr[p2] = sa.z; g_csr[p3] = sa.w;
        g_csr[p4] = sb.x; g_csr[p5] = sb.y; g_csr[p6] = sb.z; g_csr[p7] = sb.w;
    } else {
        for (int e = e0; e < E; e++)
            g_csr[atomicAdd(&g_fill[receivers[e]], 1)] = senders[e];
    }
}

// ---------------------------------------------------------------------------
// Fused node kernel: 16 lanes/node (2 nodes/warp), 4-edge unroll + tail.
// ---------------------------------------------------------------------------
__device__ __forceinline__ void accum8(float2* a, uint4 u, float w) {
    float2 p0 = __half22float2(*reinterpret_cast<__half2*>(&u.x));
    float2 p1 = __half22float2(*reinterpret_cast<__half2*>(&u.y));
    float2 p2 = __half22float2(*reinterpret_cast<__half2*>(&u.z));
    float2 p3 = __half22float2(*reinterpret_cast<__half2*>(&u.w));
    a[0].x += w * p0.x; a[0].y += w * p0.y;
    a[1].x += w * p1.x; a[1].y += w * p1.y;
    a[2].x += w * p2.x; a[2].y += w * p2.y;
    a[3].x += w * p3.x; a[3].y += w * p3.y;
}

__global__ __launch_bounds__(256)
void node_accum_kernel(float* __restrict__ out, int N) {
    int warp = (blockIdx.x * blockDim.x + threadIdx.x) >> 5;
    int lane = threadIdx.x & 31;
    int node = warp * 2 + (lane >> 4);
    int sl = lane & 15;
    if (node >= N) return;

    int start = g_row[node];
    int end   = g_row[node + 1];
    float* outp = out + (size_t)node * DIM + sl * 8;

    if (start == end) {
        *reinterpret_cast<float4*>(outp)     = make_float4(0.f, 0.f, 0.f, 0.f);
        *reinterpret_cast<float4*>(outp + 4) = make_float4(0.f, 0.f, 0.f, 0.f);
        return;
    }

    const int h2 = sl >> 1;
    const __half* ntb = g_nth;
    float2 acc[4];
    acc[0] = acc[1] = acc[2] = acc[3] = make_float2(0.f, 0.f);
    float denom = 0.0f;

    int j = start;
    for (; j + 3 < end; j += 4) {
        int s0 = __ldg(&g_csr[j]);
        int s1 = __ldg(&g_csr[j + 1]);
        int s2 = __ldg(&g_csr[j + 2]);
        int s3 = __ldg(&g_csr[j + 3]);
        float w0 = g_es[(size_t)s0 * HEADS + h2];
        float w1 = g_es[(size_t)s1 * HEADS + h2];
        float w2 = g_es[(size_t)s2 * HEADS + h2];
        float w3 = g_es[(size_t)s3 * HEADS + h2];
        uint4 u0 = *reinterpret_cast<const uint4*>(&ntb[(size_t)s0 * DIM + sl * 8]);
        uint4 u1 = *reinterpret_cast<const uint4*>(&ntb[(size_t)s1 * DIM + sl * 8]);
        uint4 u2 = *reinterpret_cast<const uint4*>(&ntb[(size_t)s2 * DIM + sl * 8]);
        uint4 u3 = *reinterpret_cast<const uint4*>(&ntb[(size_t)s3 * DIM + sl * 8]);
        accum8(acc, u0, w0);
        accum8(acc, u1, w1);
        accum8(acc, u2, w2);
        accum8(acc, u3, w3);
        denom += (w0 + w1) + (w2 + w3);
    }
    for (; j < end; j++) {
        int s0 = __ldg(&g_csr[j]);
        float w0 = g_es[(size_t)s0 * HEADS + h2];
        uint4 u0 = *reinterpret_cast<const uint4*>(&ntb[(size_t)s0 * DIM + sl * 8]);
        accum8(acc, u0, w0);
        denom += w0;
    }

    float inv = 1.0f / denom;
    *reinterpret_cast<float4*>(outp) =
        make_float4(acc[0].x * inv, acc[0].y * inv, acc[1].x * inv, acc[1].y * inv);
    *reinterpret_cast<float4*>(outp + 4) =
        make_float4(acc[2].x * inv, acc[2].y * inv, acc[3].x * inv, acc[3].y * inv);
}

// ---------------------------------------------------------------------------
extern "C" void kernel_launch(void* const* d_in, const int* in_sizes, int n_in,
                              void* d_out, int out_size) {
    const float* nodes     = (const float*)d_in[0];
    const int*   senders   = (const int*)d_in[1];
    const int*   receivers = (const int*)d_in[2];
    const float* W         = (const float*)d_in[3];
    const float* b         = (const float*)d_in[4];
    const float* attn_w    = (const float*)d_in[5];
    // attn_b (d_in[6]) cancels in the segment softmax

    const int N = in_sizes[0] / DIM;
    const int E = in_sizes[1];
    float* out = (float*)d_out;

    const int nb = (N + SCAN_BLK - 1) / SCAN_BLK;
    const int tiles = (N + 127) / 128;
    const int e8blocks = ((E + 7) / 8 + 255) / 256;

    static cudaStream_t s_side = nullptr;
    static cudaEvent_t ev_fork = nullptr, ev_join = nullptr;
    if (!s_side) {
        cudaStreamCreateWithFlags(&s_side, cudaStreamNonBlocking);
        cudaEventCreateWithFlags(&ev_fork, cudaEventDisableTiming);
        cudaEventCreateWithFlags(&ev_join, cudaEventDisableTiming);
        cudaFuncSetAttribute(gemm_mma_kernel,
                             cudaFuncAttributeMaxDynamicSharedMemorySize, SM_TOTAL);
    }

    // fork: CSR build on side stream, GEMM chain on main stream
    cudaEventRecord(ev_fork, 0);
    cudaStreamWaitEvent(s_side, ev_fork, 0);

    count_kernel<<<e8blocks, 256, 0, s_side>>>(receivers, E);
    scan1_kernel<<<nb, SCAN_BLK, 0, s_side>>>(N);
    scan23_kernel<<<(N + 255) / 256, 256, 0, s_side>>>(N, E);
    fill_kernel<<<e8blocks, 256, 0, s_side>>>(senders, receivers, E);

    prep_w_kernel<<<(DIM * DIM + 255) / 256, 256>>>(W);
    gemm_mma_kernel<<<tiles, 256, SM_TOTAL>>>(nodes, b, attn_w, N);

    // join
    cudaEventRecord(ev_join, s_side);
    cudaStreamWaitEvent(0, ev_join, 0);

    node_accum_kernel<<<(N * 16 + 255) / 256, 256>>>(out, N);
}

// round 11
// speedup vs baseline: 1.2481x; 1.0280x over previous
#include <cuda_runtime.h>
#include <cuda_bf16.h>
#include <cuda_fp16.h>
#include <cstdint>
#include <math.h>

#define DIM      128
#define HEADS    8
#define NMAX     100000
#define EMAX     1600000
#define SCAN_BLK 1024
#define MAX_BLKS ((NMAX + SCAN_BLK - 1) / SCAN_BLK + 2)

// ---------------- device scratch (allocation-free rule) ----------------
__device__ __half g_nth[(size_t)NMAX * DIM]; // transformed node features (fp16)
__device__ float g_es[(size_t)NMAX * HEADS]; // exp(sender score)
__device__ int   g_cnt[NMAX];                // in-degree counts (kept zeroed)
__device__ int   g_row[NMAX + 1];            // CSR row offsets
__device__ int   g_pos[EMAX];                // per-edge slot within its segment
__device__ int   g_csr[EMAX];                // CSR payload: sender ids
__device__ int   g_bsum[MAX_BLKS];           // scan block sums
// W as bf16 hi/lo images, layout Bt[n][k] row-major with ldmatrix swizzle
__device__ __align__(16) char g_Bhi[32768];
__device__ __align__(16) char g_Blo[32768];

__device__ __forceinline__ float lrelu(float x) { return x > 0.0f ? x : 0.2f * x; }

__device__ __forceinline__ uint32_t smem_u32(const void* p) {
    uint32_t a;
    asm("{ .reg .u64 t; cvta.to.shared.u64 t, %1; cvt.u32.u64 %0, t; }" : "=r"(a) : "l"(p));
    return a;
}

// swizzled byte offset inside a [rows][128 bf16] tile (256B rows)
__device__ __forceinline__ uint32_t toff(int row, int k) {
    return (uint32_t)(row * 256 + ((((k >> 3) ^ (row & 7)) & 15) << 4) + ((k & 7) << 1));
}

#define LDSM4(r, addr) asm volatile( \
    "ldmatrix.sync.aligned.m8n8.x4.shared.b16 {%0,%1,%2,%3}, [%4];" \
    : "=r"((r)[0]), "=r"((r)[1]), "=r"((r)[2]), "=r"((r)[3]) : "r"(addr))
#define LDSM2(r, addr) asm volatile( \
    "ldmatrix.sync.aligned.m8n8.x2.shared.b16 {%0,%1}, [%2];" \
    : "=r"((r)[0]), "=r"((r)[1]) : "r"(addr))
#define MMA(c, a, b) asm volatile( \
    "mma.sync.aligned.m16n8k16.row.col.f32.bf16.bf16.f32 " \
    "{%0,%1,%2,%3},{%4,%5,%6,%7},{%8,%9},{%0,%1,%2,%3};" \
    : "+f"((c)[0]), "+f"((c)[1]), "+f"((c)[2]), "+f"((c)[3]) \
    : "r"((a)[0]), "r"((a)[1]), "r"((a)[2]), "r"((a)[3]), "r"((b)[0]), "r"((b)[1]))

// ---------------------------------------------------------------------------
// prep: W (fp32 [k][n]) -> bf16 hi/lo Bt[n][k] swizzled images (once, global)
// ---------------------------------------------------------------------------
__global__ void prep_w_kernel(const float* __restrict__ W) {
    int t = blockIdx.x * blockDim.x + threadIdx.x;
    if (t >= DIM * DIM) return;
    int k = t >> 7, n = t & 127;
    float x = W[k * DIM + n];
    __nv_bfloat16 h = __float2bfloat16(x);
    __nv_bfloat16 l = __float2bfloat16(x - __bfloat162float(h));
    uint32_t so = toff(n, k);
    *reinterpret_cast<__nv_bfloat16*>(g_Bhi + so) = h;
    *reinterpret_cast<__nv_bfloat16*>(g_Blo + so) = l;
}

// ---------------------------------------------------------------------------
// GEMM: bf16-split mma.sync, 128-row tiles. Epilogue: +bias, store nt (fp16),
// fused per-head score -> g_es = exp(score).
// ---------------------------------------------------------------------------
#define SM_AHI 0
#define SM_ALO 32768
#define SM_BHI 65536
#define SM_BLO 98304
#define SM_TOTAL 131072

__global__ __launch_bounds__(256, 1)
void gemm_mma_kernel(const float* __restrict__ A, const float* __restrict__ bias,
                     const float* __restrict__ attn_w, int N) {
    extern __shared__ __align__(1024) char smem[];
    const uint32_t sb = smem_u32(smem);
    const int tid = threadIdx.x;
    const int wid = tid >> 5;
    const int lane = tid & 31;
    const int row0 = blockIdx.x * 128;

    {
        const int4* shi = reinterpret_cast<const int4*>(g_Bhi);
        const int4* slo = reinterpret_cast<const int4*>(g_Blo);
        int4* dhi = reinterpret_cast<int4*>(smem + SM_BHI);
        int4* dlo = reinterpret_cast<int4*>(smem + SM_BLO);
        for (int i = tid; i < 2048; i += 256) { dhi[i] = shi[i]; dlo[i] = slo[i]; }
    }
    for (int i = 0; i < 16; i++) {
        int idx4 = tid + i * 256;
        int r = idx4 >> 5;
        int c4 = (idx4 & 31) * 4;
        float4 v = make_float4(0.f, 0.f, 0.f, 0.f);
        if (row0 + r < N)
            v = *reinterpret_cast<const float4*>(&A[(size_t)(row0 + r) * DIM + c4]);
        float xs[4] = {v.x, v.y, v.z, v.w};
        __nv_bfloat16 hs[4], ls[4];
#pragma unroll
        for (int j = 0; j < 4; j++) {
            hs[j] = __float2bfloat16(xs[j]);
            ls[j] = __float2bfloat16(xs[j] - __bfloat162float(hs[j]));
        }
        uint32_t so = toff(r, c4);
        *reinterpret_cast<__nv_bfloat162*>(smem + SM_AHI + so)     = __halves2bfloat162(hs[0], hs[1]);
        *reinterpret_cast<__nv_bfloat162*>(smem + SM_AHI + so + 4) = __halves2bfloat162(hs[2], hs[3]);
        *reinterpret_cast<__nv_bfloat162*>(smem + SM_ALO + so)     = __halves2bfloat162(ls[0], ls[1]);
        *reinterpret_cast<__nv_bfloat162*>(smem + SM_ALO + so + 4) = __halves2bfloat162(ls[2], ls[3]);
    }
    __syncthreads();

    const int wm = wid >> 2;
    const int wn = wid & 3;
    const int r_base = wm * 64;
    const int n_base = wn * 32;

    float acc[4][4][4];
#pragma unroll
    for (int mi = 0; mi < 4; mi++)
#pragma unroll
        for (int ni = 0; ni < 4; ni++)
#pragma unroll
            for (int q = 0; q < 4; q++) acc[mi][ni][q] = 0.0f;

    const int L = lane & 15;
#pragma unroll
    for (int ks = 0; ks < 8; ks++) {
        uint32_t ah[4][4], al[4][4], bh[4][2], bl[4][2];
        const int ka = ks * 16 + (lane >> 4) * 8;
        const int kb = ks * 16 + ((L >> 3) & 1) * 8;
#pragma unroll
        for (int mi = 0; mi < 4; mi++) {
            uint32_t off = toff(r_base + mi * 16 + L, ka);
            LDSM4(ah[mi], sb + SM_AHI + off);
            LDSM4(al[mi], sb + SM_ALO + off);
        }
#pragma unroll
        for (int ni = 0; ni < 4; ni++) {
            uint32_t off = toff(n_base + ni * 8 + (L & 7), kb);
            LDSM2(bh[ni], sb + SM_BHI + off);
            LDSM2(bl[ni], sb + SM_BLO + off);
        }
#pragma unroll
        for (int mi = 0; mi < 4; mi++)
#pragma unroll
            for (int ni = 0; ni < 4; ni++) {
                MMA(acc[mi][ni], ah[mi], bh[ni]);
                MMA(acc[mi][ni], ah[mi], bl[ni]);
                MMA(acc[mi][ni], al[mi], bh[ni]);
            }
    }

    // ---- epilogue ----
    float aw[16];
#pragma unroll
    for (int j = 0; j < 16; j++) aw[j] = __ldg(&attn_w[j]);

    float sp[8][2];
#pragma unroll
    for (int q = 0; q < 8; q++) { sp[q][0] = 0.0f; sp[q][1] = 0.0f; }

#pragma unroll
    for (int ni = 0; ni < 4; ni++) {
        int n0 = n_base + ni * 8 + (lane & 3) * 2;
        float bw0 = __ldg(&bias[n0]), bw1 = __ldg(&bias[n0 + 1]);
        float aw0 = aw[n0 & 15], aw1 = aw[(n0 + 1) & 15];
        int hl = ni >> 1;
#pragma unroll
        for (int mi = 0; mi < 4; mi++) {
            float c0 = acc[mi][ni][0] + bw0, c1 = acc[mi][ni][1] + bw1;
            float c2 = acc[mi][ni][2] + bw0, c3 = acc[mi][ni][3] + bw1;
            int ra = row0 + r_base + mi * 16 + (lane >> 2);
            int rb = ra + 8;
            if (ra < N) *reinterpret_cast<__half2*>(&g_nth[(size_t)ra * DIM + n0]) = __floats2half2_rn(c0, c1);
            if (rb < N) *reinterpret_cast<__half2*>(&g_nth[(size_t)rb * DIM + n0]) = __floats2half2_rn(c2, c3);
            sp[mi * 2 + 0][hl] += lrelu(c0) * aw0 + lrelu(c1) * aw1;
            sp[mi * 2 + 1][hl] += lrelu(c2) * aw0 + lrelu(c3) * aw1;
        }
    }
#pragma unroll
    for (int slot = 0; slot < 8; slot++)
#pragma unroll
        for (int hl = 0; hl < 2; hl++) {
            float v = sp[slot][hl];
            v += __shfl_xor_sync(0xffffffffu, v, 1);
            v += __shfl_xor_sync(0xffffffffu, v, 2);
            if ((lane & 3) == 0) {
                int row = row0 + r_base + (slot >> 1) * 16 + (slot & 1) * 8 + (lane >> 2);
                if (row < N) g_es[(size_t)row * HEADS + wn * 2 + hl] = __expf(v);
            }
        }
}

// ---------------------------------------------------------------------------
// CSR build (side stream): count (+slot record) -> scan1 -> scan23 -> fill
// fill is atomic-free: slot recorded during count.
// ---------------------------------------------------------------------------
__global__ void count_kernel(const int* __restrict__ receivers, int E) {
    int t = blockIdx.x * blockDim.x + threadIdx.x;
    int e0 = t * 4;
    if (e0 + 3 < E) {
        int4 r = *reinterpret_cast<const int4*>(&receivers[e0]);
        int4 p;
        p.x = atomicAdd(&g_cnt[r.x], 1);
        p.y = atomicAdd(&g_cnt[r.y], 1);
        p.z = atomicAdd(&g_cnt[r.z], 1);
        p.w = atomicAdd(&g_cnt[r.w], 1);
        *reinterpret_cast<int4*>(&g_pos[e0]) = p;
    } else {
        for (int e = e0; e < E; e++)
            g_pos[e] = atomicAdd(&g_cnt[receivers[e]], 1);
    }
}

__global__ __launch_bounds__(SCAN_BLK)
void scan1_kernel(int N) {
    __shared__ int wsum[32];
    int i = blockIdx.x * SCAN_BLK + threadIdx.x;
    int lane = threadIdx.x & 31, w = threadIdx.x >> 5;
    int v = 0;
    if (i < N) { v = g_cnt[i]; g_cnt[i] = 0; }   // read + re-zero for replay
    int incl = v;
#pragma unroll
    for (int o = 1; o < 32; o <<= 1) {
        int t = __shfl_up_sync(0xffffffffu, incl, o);
        if (lane >= o) incl += t;
    }
    if (lane == 31) wsum[w] = incl;
    __syncthreads();
    if (w == 0) {
        int s = wsum[lane];
#pragma unroll
        for (int o = 1; o < 32; o <<= 1) {
            int t = __shfl_up_sync(0xffffffffu, s, o);
            if (lane >= o) s += t;
        }
        wsum[lane] = s;
    }
    __syncthreads();
    int woff = (w > 0) ? wsum[w - 1] : 0;
    if (i < N) g_row[i] = woff + incl - v;       // exclusive (block-local)
    if (threadIdx.x == SCAN_BLK - 1) g_bsum[blockIdx.x] = woff + incl;
}

// scan2 merged into scan3: warp 0 of each block reduces its g_bsum prefix.
__global__ void scan23_kernel(int N, int E) {
    __shared__ int soff;
    int i = blockIdx.x * blockDim.x + threadIdx.x;
    int g = (int)((blockIdx.x * blockDim.x) / SCAN_BLK);
    if (threadIdx.x < 32) {
        int lane = threadIdx.x;
        int acc = 0;
        for (int b = lane; b < g; b += 32) acc += g_bsum[b];
#pragma unroll
        for (int o = 16; o > 0; o >>= 1) acc += __shfl_xor_sync(0xffffffffu, acc, o);
        if (lane == 0) soff = acc;
    }
    __syncthreads();
    if (i < N) g_row[i] += soff;
    if (i == 0) g_row[N] = E;
}

// atomic-free fill: scatter stores only
__global__ void fill_kernel(const int* __restrict__ senders,
                            const int* __restrict__ receivers, int E) {
    int t = blockIdx.x * blockDim.x + threadIdx.x;
    int e0 = t * 4;
    if (e0 + 3 < E) {
        int4 r = *reinterpret_cast<const int4*>(&receivers[e0]);
        int4 s = *reinterpret_cast<const int4*>(&senders[e0]);
        int4 p = *reinterpret_cast<const int4*>(&g_pos[e0]);
        g_csr[g_row[r.x] + p.x] = s.x;
        g_csr[g_row[r.y] + p.y] = s.y;
        g_csr[g_row[r.z] + p.z] = s.z;
        g_csr[g_row[r.w] + p.w] = s.w;
    } else {
        for (int e = e0; e < E; e++)
            g_csr[g_row[receivers[e]] + g_pos[e]] = senders[e];
    }
}

// ---------------------------------------------------------------------------
// Fused node kernel: 16 lanes/node (2 nodes/warp), 4-edge unroll + tail.
// ---------------------------------------------------------------------------
__device__ __forceinline__ void accum8(float2* a, uint4 u, float w) {
    float2 p0 = __half22float2(*reinterpret_cast<__half2*>(&u.x));
    float2 p1 = __half22float2(*reinterpret_cast<__half2*>(&u.y));
    float2 p2 = __half22float2(*reinterpret_cast<__half2*>(&u.z));
    float2 p3 = __half22float2(*reinterpret_cast<__half2*>(&u.w));
    a[0].x += w * p0.x; a[0].y += w * p0.y;
    a[1].x += w * p1.x; a[1].y += w * p1.y;
    a[2].x += w * p2.x; a[2].y += w * p2.y;
    a[3].x += w * p3.x; a[3].y += w * p3.y;
}

__global__ __launch_bounds__(256)
void node_accum_kernel(float* __restrict__ out, int N) {
    int warp = (blockIdx.x * blockDim.x + threadIdx.x) >> 5;
    int lane = threadIdx.x & 31;
    int node = warp * 2 + (lane >> 4);
    int sl = lane & 15;
    if (node >= N) return;

    int start = g_row[node];
    int end   = g_row[node + 1];
    float* outp = out + (size_t)node * DIM + sl * 8;

    if (start == end) {
        *reinterpret_cast<float4*>(outp)     = make_float4(0.f, 0.f, 0.f, 0.f);
        *reinterpret_cast<float4*>(outp + 4) = make_float4(0.f, 0.f, 0.f, 0.f);
        return;
    }

    const int h2 = sl >> 1;
    const __half* ntb = g_nth;
    float2 acc[4];
    acc[0] = acc[1] = acc[2] = acc[3] = make_float2(0.f, 0.f);
    float denom = 0.0f;

    int j = start;
    for (; j + 3 < end; j += 4) {
        int s0 = __ldg(&g_csr[j]);
        int s1 = __ldg(&g_csr[j + 1]);
        int s2 = __ldg(&g_csr[j + 2]);
        int s3 = __ldg(&g_csr[j + 3]);
        float w0 = g_es[(size_t)s0 * HEADS + h2];
        float w1 = g_es[(size_t)s1 * HEADS + h2];
        float w2 = g_es[(size_t)s2 * HEADS + h2];
        float w3 = g_es[(size_t)s3 * HEADS + h2];
        uint4 u0 = *reinterpret_cast<const uint4*>(&ntb[(size_t)s0 * DIM + sl * 8]);
        uint4 u1 = *reinterpret_cast<const uint4*>(&ntb[(size_t)s1 * DIM + sl * 8]);
        uint4 u2 = *reinterpret_cast<const uint4*>(&ntb[(size_t)s2 * DIM + sl * 8]);
        uint4 u3 = *reinterpret_cast<const uint4*>(&ntb[(size_t)s3 * DIM + sl * 8]);
        accum8(acc, u0, w0);
        accum8(acc, u1, w1);
        accum8(acc, u2, w2);
        accum8(acc, u3, w3);
        denom += (w0 + w1) + (w2 + w3);
    }
    for (; j < end; j++) {
        int s0 = __ldg(&g_csr[j]);
        float w0 = g_es[(size_t)s0 * HEADS + h2];
        uint4 u0 = *reinterpret_cast<const uint4*>(&ntb[(size_t)s0 * DIM + sl * 8]);
        accum8(acc, u0, w0);
        denom += w0;
    }

    float inv = 1.0f / denom;
    *reinterpret_cast<float4*>(outp) =
        make_float4(acc[0].x * inv, acc[0].y * inv, acc[1].x * inv, acc[1].y * inv);
    *reinterpret_cast<float4*>(outp + 4) =
        make_float4(acc[2].x * inv, acc[2].y * inv, acc[3].x * inv, acc[3].y * inv);
}

// ---------------------------------------------------------------------------
extern "C" void kernel_launch(void* const* d_in, const int* in_sizes, int n_in,
                              void* d_out, int out_size) {
    const float* nodes     = (const float*)d_in[0];
    const int*   senders   = (const int*)d_in[1];
    const int*   receivers = (const int*)d_in[2];
    const float* W         = (const float*)d_in[3];
    const float* b         = (const float*)d_in[4];
    const float* attn_w    = (const float*)d_in[5];
    // attn_b (d_in[6]) cancels in the segment softmax

    const int N = in_sizes[0] / DIM;
    const int E = in_sizes[1];
    float* out = (float*)d_out;

    const int nb = (N + SCAN_BLK - 1) / SCAN_BLK;
    const int tiles = (N + 127) / 128;
    const int e4blocks = ((E + 3) / 4 + 255) / 256;

    static cudaStream_t s_side = nullptr;
    static cudaEvent_t ev_fork = nullptr, ev_join = nullptr;
    if (!s_side) {
        cudaStreamCreateWithFlags(&s_side, cudaStreamNonBlocking);
        cudaEventCreateWithFlags(&ev_fork, cudaEventDisableTiming);
        cudaEventCreateWithFlags(&ev_join, cudaEventDisableTiming);
        cudaFuncSetAttribute(gemm_mma_kernel,
                             cudaFuncAttributeMaxDynamicSharedMemorySize, SM_TOTAL);
    }

    // fork: CSR build on side stream, GEMM chain on main stream
    cudaEventRecord(ev_fork, 0);
    cudaStreamWaitEvent(s_side, ev_fork, 0);

    count_kernel<<<e4blocks, 256, 0, s_side>>>(receivers, E);
    scan1_kernel<<<nb, SCAN_BLK, 0, s_side>>>(N);
    scan23_kernel<<<(N + 255) / 256, 256, 0, s_side>>>(N, E);
    fill_kernel<<<e4blocks, 256, 0, s_side>>>(senders, receivers, E);

    prep_w_kernel<<<(DIM * DIM + 255) / 256, 256>>>(W);
    gemm_mma_kernel<<<tiles, 256, SM_TOTAL>>>(nodes, b, attn_w, N);

    // join
    cudaEventRecord(ev_join, s_side);
    cudaStreamWaitEvent(0, ev_join, 0);

    node_accum_kernel<<<(N * 16 + 255) / 256, 256>>>(out, N);
}